// round 1
// baseline (speedup 1.0000x reference)
#include <cuda_runtime.h>
#include <cuda_bf16.h>

#define T_DIM 64
#define B_DIM 16
#define S_DIM 256
#define D_DIM 512
#define T_TILE 8

// scratch: h = input @ W_comb + b_comb, stored (B, T, D)
__device__ float g_h[B_DIM * T_DIM * D_DIM];

__device__ __forceinline__ float tanh_ap(float x) {
    float y;
    asm("tanh.approx.f32 %0, %1;" : "=f"(y) : "f"(x));
    return y;
}

// ---------------------------------------------------------------------------
// Kernel 1: h[b,t,:] = input[t,b,:] @ W + bias   (M=1024 rows, N=512, K=512)
// 64x64 tile per block, 256 threads, 4x4 micro-tile per thread.
// ---------------------------------------------------------------------------
__global__ __launch_bounds__(256) void gemm_kernel(
    const float* __restrict__ A,      // input (T,B,D) flattened -> (1024, 512)
    const float* __restrict__ W,      // (512, 512)
    const float* __restrict__ bias)   // (512)
{
    __shared__ float As[64][33];
    __shared__ float Bs[32][68];

    const int tid = threadIdx.x;
    const int tx = tid & 15;          // 0..15 -> 4 output cols each
    const int ty = tid >> 4;          // 0..15 -> 4 output rows each
    const int m0 = blockIdx.y * 64;
    const int n0 = blockIdx.x * 64;

    float acc[4][4];
#pragma unroll
    for (int i = 0; i < 4; ++i)
#pragma unroll
        for (int j = 0; j < 4; ++j) acc[i][j] = 0.f;

    for (int k0 = 0; k0 < D_DIM; k0 += 32) {
        // A tile 64x32 (coalesced: 32-float rows)
#pragma unroll
        for (int i = tid; i < 64 * 32; i += 256) {
            int r = i >> 5, c = i & 31;
            As[r][c] = A[(size_t)(m0 + r) * D_DIM + k0 + c];
        }
        // W tile 32x64 (coalesced: 64-float rows)
#pragma unroll
        for (int i = tid; i < 32 * 64; i += 256) {
            int r = i >> 6, c = i & 63;
            Bs[r][c] = W[(size_t)(k0 + r) * D_DIM + n0 + c];
        }
        __syncthreads();

#pragma unroll
        for (int k = 0; k < 32; ++k) {
            float4 b4 = *(const float4*)&Bs[k][tx * 4];
            float a0 = As[ty * 4 + 0][k];
            float a1 = As[ty * 4 + 1][k];
            float a2 = As[ty * 4 + 2][k];
            float a3 = As[ty * 4 + 3][k];
            acc[0][0] += a0 * b4.x; acc[0][1] += a0 * b4.y; acc[0][2] += a0 * b4.z; acc[0][3] += a0 * b4.w;
            acc[1][0] += a1 * b4.x; acc[1][1] += a1 * b4.y; acc[1][2] += a1 * b4.z; acc[1][3] += a1 * b4.w;
            acc[2][0] += a2 * b4.x; acc[2][1] += a2 * b4.y; acc[2][2] += a2 * b4.z; acc[2][3] += a2 * b4.w;
            acc[3][0] += a3 * b4.x; acc[3][1] += a3 * b4.y; acc[3][2] += a3 * b4.z; acc[3][3] += a3 * b4.w;
        }
        __syncthreads();
    }

    // writeback with bias; remap row m = t*B + b  ->  g_h[(b*T + t)*D + n]
#pragma unroll
    for (int i = 0; i < 4; ++i) {
        int m = m0 + ty * 4 + i;
        int bb = m & (B_DIM - 1);
        int tt = m >> 4;
        float* dst = &g_h[((size_t)bb * T_DIM + tt) * D_DIM + n0 + tx * 4];
#pragma unroll
        for (int j = 0; j < 4; ++j)
            dst[j] = acc[i][j] + bias[n0 + tx * 4 + j];
    }
}

// ---------------------------------------------------------------------------
// Kernel 2: fused additive-attention.
// grid = (B, T/T_TILE), 256 threads (8 warps).
//   phase 1: warp-per-s logits   logit[t,s] = sum_d vw[d]*tanh(h[t,d]+c[s,d])
//   phase 2: warp-per-t softmax over S
//   phase 3: thread-per-d AV:    out[t,d] = sum_s attn[t,s]*values[s,d]
// ---------------------------------------------------------------------------
__global__ __launch_bounds__(256) void attn_kernel(
    const float* __restrict__ context,   // (B,S,D)
    const float* __restrict__ values,    // (B,S,D)
    const float* __restrict__ v_w,       // (D)
    const float* __restrict__ v_b,       // scalar
    float* __restrict__ out_w,           // (T,B,D)
    float* __restrict__ out_attn)        // (B*T, S)
{
    __shared__ float h_s[T_TILE * D_DIM];      // 16 KB
    __shared__ float vw_s[D_DIM];              // 2 KB
    __shared__ float lg[T_TILE][S_DIM];        // 8 KB
    __shared__ float red_inv[T_TILE];

    const int b  = blockIdx.x;
    const int t0 = blockIdx.y * T_TILE;
    const int tid = threadIdx.x;
    const int wid = tid >> 5;
    const int lane = tid & 31;

    const float* hp = g_h + ((size_t)b * T_DIM + t0) * D_DIM;
    for (int i = tid; i < T_TILE * D_DIM; i += 256) h_s[i] = hp[i];
    for (int i = tid; i < D_DIM; i += 256) vw_s[i] = v_w[i];
    __syncthreads();

    const float vb = v_b[0];
    const float4* h4  = (const float4*)h_s;
    const float4* vw4 = (const float4*)vw_s;
    const float4* cb  = (const float4*)(context + (size_t)b * S_DIM * D_DIM);

    // ---- phase 1: logits (warp wid handles s = wid*32 .. wid*32+31) ----
    for (int si = 0; si < 32; ++si) {
        int s = wid * 32 + si;
        const float4* c4 = cb + (size_t)s * (D_DIM / 4);
        float acc[T_TILE];
#pragma unroll
        for (int t = 0; t < T_TILE; ++t) acc[t] = 0.f;

#pragma unroll
        for (int j = 0; j < 4; ++j) {
            float4 cc = c4[j * 32 + lane];
            float4 ww = vw4[j * 32 + lane];
#pragma unroll
            for (int t = 0; t < T_TILE; ++t) {
                float4 hh = h4[t * (D_DIM / 4) + j * 32 + lane];
                acc[t] += ww.x * tanh_ap(hh.x + cc.x);
                acc[t] += ww.y * tanh_ap(hh.y + cc.y);
                acc[t] += ww.z * tanh_ap(hh.z + cc.z);
                acc[t] += ww.w * tanh_ap(hh.w + cc.w);
            }
        }
#pragma unroll
        for (int t = 0; t < T_TILE; ++t) {
            float v = acc[t];
            v += __shfl_xor_sync(0xffffffffu, v, 16);
            v += __shfl_xor_sync(0xffffffffu, v, 8);
            v += __shfl_xor_sync(0xffffffffu, v, 4);
            v += __shfl_xor_sync(0xffffffffu, v, 2);
            v += __shfl_xor_sync(0xffffffffu, v, 1);
            if (lane == 0) lg[t][s] = v + vb;
        }
    }
    __syncthreads();

    // ---- phase 2: softmax over S, warp wid owns row t = wid ----
    {
        float m = -1e30f;
        for (int i = lane; i < S_DIM; i += 32) m = fmaxf(m, lg[wid][i]);
#pragma unroll
        for (int o = 16; o; o >>= 1) m = fmaxf(m, __shfl_xor_sync(0xffffffffu, m, o));
        float ssum = 0.f;
        for (int i = lane; i < S_DIM; i += 32) {
            float e = __expf(lg[wid][i] - m);
            lg[wid][i] = e;
            ssum += e;
        }
#pragma unroll
        for (int o = 16; o; o >>= 1) ssum += __shfl_xor_sync(0xffffffffu, ssum, o);
        if (lane == 0) red_inv[wid] = 1.0f / ssum;
    }
    __syncthreads();

    // normalize, write attn output (coalesced), keep normalized probs in smem
#pragma unroll
    for (int t = 0; t < T_TILE; ++t) {
        float p = lg[t][tid] * red_inv[t];
        lg[t][tid] = p;
        out_attn[((size_t)b * T_DIM + t0 + t) * S_DIM + tid] = p;
    }
    __syncthreads();

    // ---- phase 3: weighted = attn @ values; thread owns cols tid, tid+256 ----
    float w0[T_TILE], w1[T_TILE];
#pragma unroll
    for (int t = 0; t < T_TILE; ++t) { w0[t] = 0.f; w1[t] = 0.f; }
    const float* vp = values + (size_t)b * S_DIM * D_DIM;
    for (int s2 = 0; s2 < S_DIM; ++s2) {
        float v0 = vp[(size_t)s2 * D_DIM + tid];
        float v1 = vp[(size_t)s2 * D_DIM + 256 + tid];
#pragma unroll
        for (int t = 0; t < T_TILE; ++t) {
            float p = lg[t][s2];
            w0[t] += p * v0;
            w1[t] += p * v1;
        }
    }
#pragma unroll
    for (int t = 0; t < T_TILE; ++t) {
        out_w[((size_t)(t0 + t) * B_DIM + b) * D_DIM + tid]       = w0[t];
        out_w[((size_t)(t0 + t) * B_DIM + b) * D_DIM + 256 + tid] = w1[t];
    }
}

// ---------------------------------------------------------------------------
extern "C" void kernel_launch(void* const* d_in, const int* in_sizes, int n_in,
                              void* d_out, int out_size) {
    const float* input   = (const float*)d_in[0];  // (T,B,D)
    const float* context = (const float*)d_in[1];  // (B,S,D)
    const float* values  = (const float*)d_in[2];  // (B,S,D)
    const float* W_comb  = (const float*)d_in[3];  // (D,D)
    const float* b_comb  = (const float*)d_in[4];  // (D)
    const float* v_w     = (const float*)d_in[5];  // (D)
    const float* v_b     = (const float*)d_in[6];  // scalar

    float* out_weighted = (float*)d_out;                               // (T,B,D)
    float* out_attn     = (float*)d_out + (size_t)T_DIM * B_DIM * D_DIM; // (B*T,S)

    dim3 g1(D_DIM / 64, (T_DIM * B_DIM) / 64);   // (8, 16)
    gemm_kernel<<<g1, 256>>>(input, W_comb, b_comb);

    dim3 g2(B_DIM, T_DIM / T_TILE);              // (16, 8)
    attn_kernel<<<g2, 256>>>(context, values, v_w, v_b, out_weighted, out_attn);
}

// round 2
// speedup vs baseline: 1.4228x; 1.4228x over previous
#include <cuda_runtime.h>
#include <cuda_bf16.h>

#define T_DIM 64
#define B_DIM 16
#define S_DIM 256
#define D_DIM 512
#define T_TILE 8

// scratch: h = input @ W_comb + b_comb, stored (B, T, D)
__device__ float g_h[B_DIM * T_DIM * D_DIM];

__device__ __forceinline__ float tanh_ap(float x) {
    float y;
    asm("tanh.approx.f32 %0, %1;" : "=f"(y) : "f"(x));
    return y;
}

// ---------------------------------------------------------------------------
// Kernel 1: h[b,t,:] = input[t,b,:] @ W + bias   (M=1024 rows, N=512, K=512)
// 64x64 tile per block, 256 threads, 4x4 micro-tile per thread.
// ---------------------------------------------------------------------------
__global__ __launch_bounds__(256) void gemm_kernel(
    const float* __restrict__ A,      // input (T,B,D) flattened -> (1024, 512)
    const float* __restrict__ W,      // (512, 512)
    const float* __restrict__ bias)   // (512)
{
    __shared__ float As[64][33];
    __shared__ float Bs[32][68];

    const int tid = threadIdx.x;
    const int tx = tid & 15;
    const int ty = tid >> 4;
    const int m0 = blockIdx.y * 64;
    const int n0 = blockIdx.x * 64;

    float acc[4][4];
#pragma unroll
    for (int i = 0; i < 4; ++i)
#pragma unroll
        for (int j = 0; j < 4; ++j) acc[i][j] = 0.f;

    for (int k0 = 0; k0 < D_DIM; k0 += 32) {
#pragma unroll
        for (int i = tid; i < 64 * 32; i += 256) {
            int r = i >> 5, c = i & 31;
            As[r][c] = A[(size_t)(m0 + r) * D_DIM + k0 + c];
        }
#pragma unroll
        for (int i = tid; i < 32 * 64; i += 256) {
            int r = i >> 6, c = i & 63;
            Bs[r][c] = W[(size_t)(k0 + r) * D_DIM + n0 + c];
        }
        __syncthreads();

#pragma unroll
        for (int k = 0; k < 32; ++k) {
            float4 b4 = *(const float4*)&Bs[k][tx * 4];
            float a0 = As[ty * 4 + 0][k];
            float a1 = As[ty * 4 + 1][k];
            float a2 = As[ty * 4 + 2][k];
            float a3 = As[ty * 4 + 3][k];
            acc[0][0] += a0 * b4.x; acc[0][1] += a0 * b4.y; acc[0][2] += a0 * b4.z; acc[0][3] += a0 * b4.w;
            acc[1][0] += a1 * b4.x; acc[1][1] += a1 * b4.y; acc[1][2] += a1 * b4.z; acc[1][3] += a1 * b4.w;
            acc[2][0] += a2 * b4.x; acc[2][1] += a2 * b4.y; acc[2][2] += a2 * b4.z; acc[2][3] += a2 * b4.w;
            acc[3][0] += a3 * b4.x; acc[3][1] += a3 * b4.y; acc[3][2] += a3 * b4.z; acc[3][3] += a3 * b4.w;
        }
        __syncthreads();
    }

#pragma unroll
    for (int i = 0; i < 4; ++i) {
        int m = m0 + ty * 4 + i;
        int bb = m & (B_DIM - 1);
        int tt = m >> 4;
        float* dst = &g_h[((size_t)bb * T_DIM + tt) * D_DIM + n0 + tx * 4];
#pragma unroll
        for (int j = 0; j < 4; ++j)
            dst[j] = acc[i][j] + bias[n0 + tx * 4 + j];
    }
}

// ---------------------------------------------------------------------------
// Kernel 2: fused additive-attention. grid=(B, T/8), 512 threads (16 warps).
// Warp w: half = w&1 (which 256-dim slice of D), sg = w>>1 (which 32 s's).
// Phase 1: each warp computes PARTIAL logits over its D-half for its 32 s's,
//          with h/v_w held in registers (si-invariant) and context prefetched.
// Phase 2: warps 0..7 combine halves + softmax row t=wid.
// Phase 3: thread-per-d (d = tid, exactly 512) AV gemv, float4 over s.
// ---------------------------------------------------------------------------
__global__ __launch_bounds__(512) void attn_kernel(
    const float* __restrict__ context,   // (B,S,D)
    const float* __restrict__ values,    // (B,S,D)
    const float* __restrict__ v_w,       // (D)
    const float* __restrict__ v_b,       // scalar
    float* __restrict__ out_w,           // (T,B,D)
    float* __restrict__ out_attn)        // (B*T, S)
{
    __shared__ float h_s[T_TILE * D_DIM];            // 16 KB
    __shared__ float lg[2][T_TILE][S_DIM];           // 16 KB (partial logits)
    __shared__ float red_inv[T_TILE];

    const int b   = blockIdx.x;
    const int t0  = blockIdx.y * T_TILE;
    const int tid = threadIdx.x;
    const int wid = tid >> 5;
    const int lane = tid & 31;
    const int half = wid & 1;        // which 256-dim slice
    const int sg   = wid >> 1;       // which group of 32 s values

    // stage h tile (coalesced float4)
    {
        const float4* hp = (const float4*)(g_h + ((size_t)b * T_DIM + t0) * D_DIM);
        float4* hs4 = (float4*)h_s;
        for (int i = tid; i < T_TILE * D_DIM / 4; i += 512) hs4[i] = hp[i];
    }
    __syncthreads();

    // ---- phase 1 ----
    {
        // register-resident h slice: 8 t x 2 chunks x float4  (64 regs)
        const int dof = half * 64 + lane;                 // float4 index within row
        const float4* h4 = (const float4*)h_s;
        float4 hh[T_TILE][2];
#pragma unroll
        for (int t = 0; t < T_TILE; ++t) {
            hh[t][0] = h4[t * (D_DIM / 4) + dof];
            hh[t][1] = h4[t * (D_DIM / 4) + dof + 32];
        }
        const float4* vw4 = (const float4*)v_w;
        float4 ww0 = vw4[dof];
        float4 ww1 = vw4[dof + 32];

        const float4* cbase = (const float4*)(context + (size_t)b * S_DIM * D_DIM)
                              + (size_t)(sg * 32) * (D_DIM / 4) + dof;

        float4 c0 = cbase[0];
        float4 c1 = cbase[32];

        for (int si = 0; si < 32; ++si) {
            float4 n0, n1;
            if (si < 31) {
                n0 = cbase[(si + 1) * (D_DIM / 4)];
                n1 = cbase[(si + 1) * (D_DIM / 4) + 32];
            }
            float acc[T_TILE];
#pragma unroll
            for (int t = 0; t < T_TILE; ++t) {
                float a;
                a  = ww0.x * tanh_ap(hh[t][0].x + c0.x);
                a += ww0.y * tanh_ap(hh[t][0].y + c0.y);
                a += ww0.z * tanh_ap(hh[t][0].z + c0.z);
                a += ww0.w * tanh_ap(hh[t][0].w + c0.w);
                a += ww1.x * tanh_ap(hh[t][1].x + c1.x);
                a += ww1.y * tanh_ap(hh[t][1].y + c1.y);
                a += ww1.z * tanh_ap(hh[t][1].z + c1.z);
                a += ww1.w * tanh_ap(hh[t][1].w + c1.w);
                acc[t] = a;
            }
#pragma unroll
            for (int t = 0; t < T_TILE; ++t) {
                float v = acc[t];
                v += __shfl_xor_sync(0xffffffffu, v, 16);
                v += __shfl_xor_sync(0xffffffffu, v, 8);
                v += __shfl_xor_sync(0xffffffffu, v, 4);
                v += __shfl_xor_sync(0xffffffffu, v, 2);
                v += __shfl_xor_sync(0xffffffffu, v, 1);
                if (lane == 0) lg[half][t][sg * 32 + si] = v;
            }
            c0 = n0; c1 = n1;
        }
    }
    __syncthreads();

    // ---- phase 2: softmax (warps 0..7, row t = wid) ----
    if (wid < T_TILE) {
        const float vb = v_b[0];
        const int t = wid;
        float e[8];
        float m = -1e30f;
#pragma unroll
        for (int k = 0; k < 8; ++k) {
            int i = k * 32 + lane;
            e[k] = lg[0][t][i] + lg[1][t][i] + vb;
            m = fmaxf(m, e[k]);
        }
#pragma unroll
        for (int o = 16; o; o >>= 1) m = fmaxf(m, __shfl_xor_sync(0xffffffffu, m, o));
        float ssum = 0.f;
#pragma unroll
        for (int k = 0; k < 8; ++k) {
            e[k] = __expf(e[k] - m);
            ssum += e[k];
        }
#pragma unroll
        for (int o = 16; o; o >>= 1) ssum += __shfl_xor_sync(0xffffffffu, ssum, o);
        const float inv = 1.0f / ssum;
        float* oa = out_attn + ((size_t)b * T_DIM + t0 + t) * S_DIM;
#pragma unroll
        for (int k = 0; k < 8; ++k) {
            float p = e[k] * inv;
            lg[0][t][k * 32 + lane] = p;   // normalized probs for AV phase
            oa[k * 32 + lane] = p;
        }
    }
    __syncthreads();

    // ---- phase 3: weighted = attn @ values; thread owns column d = tid ----
    {
        float w[T_TILE];
#pragma unroll
        for (int t = 0; t < T_TILE; ++t) w[t] = 0.f;
        const float* vp = values + (size_t)b * S_DIM * D_DIM + tid;
        for (int s = 0; s < S_DIM; s += 4) {
            float v0 = vp[(size_t)(s + 0) * D_DIM];
            float v1 = vp[(size_t)(s + 1) * D_DIM];
            float v2 = vp[(size_t)(s + 2) * D_DIM];
            float v3 = vp[(size_t)(s + 3) * D_DIM];
#pragma unroll
            for (int t = 0; t < T_TILE; ++t) {
                float4 p = *(const float4*)&lg[0][t][s];
                w[t] += p.x * v0 + p.y * v1 + p.z * v2 + p.w * v3;
            }
        }
#pragma unroll
        for (int t = 0; t < T_TILE; ++t)
            out_w[((size_t)(t0 + t) * B_DIM + b) * D_DIM + tid] = w[t];
    }
}

// ---------------------------------------------------------------------------
extern "C" void kernel_launch(void* const* d_in, const int* in_sizes, int n_in,
                              void* d_out, int out_size) {
    const float* input   = (const float*)d_in[0];
    const float* context = (const float*)d_in[1];
    const float* values  = (const float*)d_in[2];
    const float* W_comb  = (const float*)d_in[3];
    const float* b_comb  = (const float*)d_in[4];
    const float* v_w     = (const float*)d_in[5];
    const float* v_b     = (const float*)d_in[6];

    float* out_weighted = (float*)d_out;                                 // (T,B,D)
    float* out_attn     = (float*)d_out + (size_t)T_DIM * B_DIM * D_DIM; // (B*T,S)

    dim3 g1(D_DIM / 64, (T_DIM * B_DIM) / 64);
    gemm_kernel<<<g1, 256>>>(input, W_comb, b_comb);

    dim3 g2(B_DIM, T_DIM / T_TILE);
    attn_kernel<<<g2, 512>>>(context, values, v_w, v_b, out_weighted, out_attn);
}